// round 10
// baseline (speedup 1.0000x reference)
#include <cuda_runtime.h>
#include <cuda_bf16.h>
#include <math.h>
#include <stdint.h>

#define Bb 4
#define Ll 1024
#define Ee 1024
#define Hh 16
#define DHh 64
#define TOPKk 32

// -------- scratch (no allocs allowed) --------
__device__ float g_q [Bb*Ll*Ee];
__device__ float g_k [Bb*Ll*Ee];
__device__ float g_v [Bb*Ll*Ee];
__device__ float g_ao[Bb*Ll*Ee];

// v path (side stream)
__device__ __nv_bfloat16 g_vs1[Bb*Ll*Ee];
__device__ __nv_bfloat16 g_vs2[Bb*Ll*Ee];
__device__ __nv_bfloat16 g_wv1[Ee*Ee];
__device__ __nv_bfloat16 g_wv2[Ee*Ee];
__device__ __nv_bfloat16 g_wo1[Ee*Ee];
__device__ __nv_bfloat16 g_wo2[Ee*Ee];

// attention filter path
__device__ __nv_bfloat16 g_qb[Bb*Ll*Ee];
__device__ __nv_bfloat16 g_kb[Bb*Ll*Ee];
__device__ __nv_bfloat16 g_sapp[(size_t)Bb*Hh*Ll*Ll];   // 128 MB approx logits

// ============================================================
// Scalar fp32 GEMM — exact round-1 version (bit-identical)
// ============================================================
#define GBM 128
#define GBN 128
#define GBK 16

__global__ __launch_bounds__(256) void gemm_nt_bias(
    const float* __restrict__ X, const float* __restrict__ W,
    const float* __restrict__ bias, float* __restrict__ out,
    int M, int N, int K)
{
    __shared__ float As[GBK][GBM];
    __shared__ float Bs[GBK][GBN];

    const int tid = threadIdx.x;
    const int bm = blockIdx.y * GBM;
    const int bn = blockIdx.x * GBN;

    const int tr = (tid / 16) * 8;
    const int tc = (tid % 16) * 8;

    const int arow  = tid >> 2;
    const int acol4 = tid & 3;

    float acc[8][8] = {};

    for (int k0 = 0; k0 < K; k0 += GBK) {
        #pragma unroll
        for (int r = 0; r < 2; r++) {
            int row = arow + r * 64;
            float4 v = *(const float4*)(X + (size_t)(bm + row) * K + k0 + acol4 * 4);
            As[acol4*4+0][row] = v.x;
            As[acol4*4+1][row] = v.y;
            As[acol4*4+2][row] = v.z;
            As[acol4*4+3][row] = v.w;
        }
        #pragma unroll
        for (int r = 0; r < 2; r++) {
            int row = arow + r * 64;
            float4 v = *(const float4*)(W + (size_t)(bn + row) * K + k0 + acol4 * 4);
            Bs[acol4*4+0][row] = v.x;
            Bs[acol4*4+1][row] = v.y;
            Bs[acol4*4+2][row] = v.z;
            Bs[acol4*4+3][row] = v.w;
        }
        __syncthreads();

        #pragma unroll
        for (int k = 0; k < GBK; k++) {
            float ra[8], rb[8];
            #pragma unroll
            for (int i = 0; i < 8; i++) ra[i] = As[k][tr + i];
            #pragma unroll
            for (int j = 0; j < 8; j++) rb[j] = Bs[k][tc + j];
            #pragma unroll
            for (int i = 0; i < 8; i++)
                #pragma unroll
                for (int j = 0; j < 8; j++)
                    acc[i][j] = fmaf(ra[i], rb[j], acc[i][j]);
        }
        __syncthreads();
    }

    #pragma unroll
    for (int i = 0; i < 8; i++) {
        #pragma unroll
        for (int j = 0; j < 8; j++) {
            out[(size_t)(bm + tr + i) * N + bn + tc + j] = acc[i][j] + bias[bn + tc + j];
        }
    }
}

// ============================================================
// casts / splits
// ============================================================
__global__ void split2_kernel(const float* __restrict__ src,
                              __nv_bfloat16* __restrict__ p1,
                              __nv_bfloat16* __restrict__ p2, int n)
{
    int i = blockIdx.x * blockDim.x + threadIdx.x;
    if (i >= n) return;
    float x = src[i];
    __nv_bfloat16 b1 = __float2bfloat16_rn(x);
    float r1 = x - __bfloat162float(b1);
    p1[i] = b1;
    p2[i] = __float2bfloat16_rn(r1);
}

__global__ void cast_bf16_kernel(const float* __restrict__ src,
                                 __nv_bfloat16* __restrict__ dst, int n)
{
    int i = blockIdx.x * blockDim.x + threadIdx.x;
    if (i < n) dst[i] = __float2bfloat16_rn(src[i]);
}

// ============================================================
// mma helpers
// ============================================================
__device__ __forceinline__ void mma16816(
    float& d0, float& d1, float& d2, float& d3,
    uint32_t a0, uint32_t a1, uint32_t a2, uint32_t a3,
    uint32_t b0, uint32_t b1)
{
    asm volatile(
        "mma.sync.aligned.m16n8k16.row.col.f32.bf16.bf16.f32 "
        "{%0,%1,%2,%3}, {%4,%5,%6,%7}, {%8,%9}, {%0,%1,%2,%3};"
        : "+f"(d0), "+f"(d1), "+f"(d2), "+f"(d3)
        : "r"(a0), "r"(a1), "r"(a2), "r"(a3), "r"(b0), "r"(b1));
}
__device__ __forceinline__ void ldsm_x4(uint32_t& r0, uint32_t& r1,
                                        uint32_t& r2, uint32_t& r3, uint32_t saddr)
{
    asm volatile("ldmatrix.sync.aligned.m8n8.x4.shared.b16 {%0,%1,%2,%3}, [%4];"
        : "=r"(r0), "=r"(r1), "=r"(r2), "=r"(r3) : "r"(saddr));
}
__device__ __forceinline__ uint32_t smem_u32(const void* p) {
    uint32_t a;
    asm("{ .reg .u64 t; cvta.to.shared.u64 t, %1; cvt.u32.u64 %0, t; }" : "=r"(a) : "l"(p));
    return a;
}
__device__ __forceinline__ void cp_async16(uint32_t saddr, const void* g) {
    asm volatile("cp.async.cg.shared.global [%0], [%1], 16;" :: "r"(saddr), "l"(g));
}
#define CP_COMMIT() asm volatile("cp.async.commit_group;" ::: "memory")
#define CP_WAIT(n)  asm volatile("cp.async.wait_group %0;" :: "n"(n) : "memory")

#define TK 1024
#define TN 1024
#define NCHUNK (TK / 32)
#define SROWB 80
#define TILE_B (128 * SROWB)
#define STAGE_B (4 * TILE_B)
#define TG_SMEM (2 * STAGE_B)

// ============================================================
// 3-term bf16x2 GEMM (v / out projections) — round-7 version
// ============================================================
__global__ __launch_bounds__(256, 2) void gemm_bf16x2_mma(
    const __nv_bfloat16* __restrict__ A1, const __nv_bfloat16* __restrict__ A2,
    const __nv_bfloat16* __restrict__ B1, const __nv_bfloat16* __restrict__ B2,
    const float* __restrict__ bias, float* __restrict__ out)
{
    extern __shared__ char smem[];
    const uint32_t smem_b = smem_u32(smem);

    const int tid = threadIdx.x;
    const int wid = tid >> 5;
    const int lane = tid & 31;
    const int g  = lane >> 2;
    const int tg = lane & 3;

    const int bm = blockIdx.y * 128;
    const int bn = blockIdx.x * 128;
    const int wm = (wid >> 1) * 32;
    const int wn = (wid & 1) * 64;

    const uint32_t lrow = (uint32_t)(lane & 15);
    const uint32_t lcol = (uint32_t)((lane >> 4) << 3);

    const __nv_bfloat16* gp[4] = {A1, A2, B1, B2};
    const int gbase[4] = {bm, bm, bn, bn};

    float acc[2][8][4] = {};

    for (int kc = 0; kc < NCHUNK + 1; kc++) {
        if (kc < NCHUNK) {
            const int k0 = kc * 32;
            const uint32_t stage_off = (uint32_t)(kc & 1) * STAGE_B;
            #pragma unroll
            for (int it = 0; it < 8; it++) {
                int c = tid + it * 256;
                int t = c >> 9;
                int rem = c & 511;
                int row = rem >> 2;
                int seg = rem & 3;
                uint32_t sa = smem_b + stage_off + (uint32_t)t * TILE_B
                            + (uint32_t)row * SROWB + (uint32_t)seg * 16;
                const __nv_bfloat16* gsrc = gp[t] + (size_t)(gbase[t] + row) * TK + k0 + seg * 8;
                cp_async16(sa, gsrc);
            }
            CP_COMMIT();
        }
        if (kc == 0) continue;

        if (kc < NCHUNK) { CP_WAIT(1); } else { CP_WAIT(0); }
        __syncthreads();

        const uint32_t st_u = smem_b + (uint32_t)((kc - 1) & 1) * STAGE_B;

        #pragma unroll
        for (int ks = 0; ks < 2; ks++) {
            const uint32_t coff = (uint32_t)(ks * 16) * 2 + lcol * 2;

            uint32_t af[2][2][4];
            #pragma unroll
            for (int p = 0; p < 2; p++)
                #pragma unroll
                for (int mt = 0; mt < 2; mt++) {
                    uint32_t addr = st_u + (uint32_t)p * TILE_B
                                  + ((uint32_t)(wm + mt * 16) + lrow) * SROWB + coff;
                    ldsm_x4(af[p][mt][0], af[p][mt][1], af[p][mt][2], af[p][mt][3], addr);
                }
            #pragma unroll
            for (int np = 0; np < 4; np++) {
                uint32_t bf[2][2][2];
                #pragma unroll
                for (int p = 0; p < 2; p++) {
                    uint32_t addr = st_u + (uint32_t)(2 + p) * TILE_B
                                  + ((uint32_t)(wn + np * 16) + lrow) * SROWB + coff;
                    ldsm_x4(bf[p][0][0], bf[p][1][0], bf[p][0][1], bf[p][1][1], addr);
                }
                #pragma unroll
                for (int ntl = 0; ntl < 2; ntl++) {
                    const int nt = np * 2 + ntl;
                    #pragma unroll
                    for (int mt = 0; mt < 2; mt++) {
                        mma16816(acc[mt][nt][0], acc[mt][nt][1], acc[mt][nt][2], acc[mt][nt][3],
                                 af[0][mt][0], af[0][mt][1], af[0][mt][2], af[0][mt][3],
                                 bf[0][ntl][0], bf[0][ntl][1]);
                        mma16816(acc[mt][nt][0], acc[mt][nt][1], acc[mt][nt][2], acc[mt][nt][3],
                                 af[0][mt][0], af[0][mt][1], af[0][mt][2], af[0][mt][3],
                                 bf[1][ntl][0], bf[1][ntl][1]);
                        mma16816(acc[mt][nt][0], acc[mt][nt][1], acc[mt][nt][2], acc[mt][nt][3],
                                 af[1][mt][0], af[1][mt][1], af[1][mt][2], af[1][mt][3],
                                 bf[0][ntl][0], bf[0][ntl][1]);
                    }
                }
            }
        }
        __syncthreads();
    }

    #pragma unroll
    for (int mt = 0; mt < 2; mt++) {
        #pragma unroll
        for (int nt = 0; nt < 8; nt++) {
            int m0 = bm + wm + mt * 16 + g;
            int n0 = bn + wn + nt * 8 + tg * 2;
            float b0 = bias[n0], b1 = bias[n0 + 1];
            float2 lo = make_float2(acc[mt][nt][0] + b0, acc[mt][nt][1] + b1);
            float2 hi = make_float2(acc[mt][nt][2] + b0, acc[mt][nt][3] + b1);
            *(float2*)(out + (size_t)m0 * TN + n0)       = lo;
            *(float2*)(out + (size_t)(m0 + 8) * TN + n0) = hi;
        }
    }
}

// ============================================================
// Filter kernel: approx logits (pure bf16 mma), S~ = QK^T/8 -> bf16 gmem.
// block = (ktile 128, qtile 128, bh). 256 threads. Single k-pass (d=64).
// ============================================================
#define FROWB 144   // 64 bf16 = 128B + 16B pad

__global__ __launch_bounds__(256) void filter_scores_kernel(
    const __nv_bfloat16* __restrict__ qb, const __nv_bfloat16* __restrict__ kb,
    __nv_bfloat16* __restrict__ sapp)
{
    __shared__ char sA[128 * FROWB];
    __shared__ char sB[128 * FROWB];

    const int tid = threadIdx.x;
    const int wid = tid >> 5;
    const int lane = tid & 31;
    const int g  = lane >> 2;
    const int tg = lane & 3;

    const int bh = blockIdx.z;
    const int b  = bh >> 4;
    const int h  = bh & 15;
    const int q0 = blockIdx.y * 128;
    const int k0 = blockIdx.x * 128;

    #pragma unroll
    for (int it = 0; it < 4; it++) {
        int idx = tid + it * 256;       // 0..1023
        int row = idx >> 3;
        int seg = idx & 7;
        *(uint4*)(sA + row * FROWB + seg * 16) =
            *(const uint4*)(qb + ((size_t)(b * Ll + q0 + row)) * Ee + h * 64 + seg * 8);
        *(uint4*)(sB + row * FROWB + seg * 16) =
            *(const uint4*)(kb + ((size_t)(b * Ll + k0 + row)) * Ee + h * 64 + seg * 8);
    }
    __syncthreads();

    const uint32_t sAu = smem_u32(sA);
    const uint32_t sBu = smem_u32(sB);
    const int wm = (wid >> 1) * 32;
    const int wn = (wid & 1) * 64;
    const uint32_t lrow = (uint32_t)(lane & 15);
    const uint32_t lcol16 = (uint32_t)((lane >> 4) * 16);

    float acc[2][8][4] = {};

    #pragma unroll
    for (int ks = 0; ks < 4; ks++) {
        const uint32_t coff = (uint32_t)ks * 32 + lcol16;
        uint32_t af[2][4];
        #pragma unroll
        for (int mt = 0; mt < 2; mt++) {
            uint32_t addr = sAu + ((uint32_t)(wm + mt * 16) + lrow) * FROWB + coff;
            ldsm_x4(af[mt][0], af[mt][1], af[mt][2], af[mt][3], addr);
        }
        #pragma unroll
        for (int np = 0; np < 4; np++) {
            uint32_t bf[2][2];
            uint32_t addr = sBu + ((uint32_t)(wn + np * 16) + lrow) * FROWB + coff;
            ldsm_x4(bf[0][0], bf[1][0], bf[0][1], bf[1][1], addr);
            #pragma unroll
            for (int ntl = 0; ntl < 2; ntl++) {
                const int nt = np * 2 + ntl;
                #pragma unroll
                for (int mt = 0; mt < 2; mt++)
                    mma16816(acc[mt][nt][0], acc[mt][nt][1], acc[mt][nt][2], acc[mt][nt][3],
                             af[mt][0], af[mt][1], af[mt][2], af[mt][3],
                             bf[ntl][0], bf[ntl][1]);
            }
        }
    }

    __nv_bfloat16* srow = sapp + (size_t)bh * Ll * Ll;
    #pragma unroll
    for (int mt = 0; mt < 2; mt++) {
        #pragma unroll
        for (int nt = 0; nt < 8; nt++) {
            int m0 = q0 + wm + mt * 16 + g;
            int n0 = k0 + wn + nt * 8 + tg * 2;
            __nv_bfloat162 lo, hi;
            lo.x = __float2bfloat16_rn(acc[mt][nt][0] * 0.125f);
            lo.y = __float2bfloat16_rn(acc[mt][nt][1] * 0.125f);
            hi.x = __float2bfloat16_rn(acc[mt][nt][2] * 0.125f);
            hi.y = __float2bfloat16_rn(acc[mt][nt][3] * 0.125f);
            *(__nv_bfloat162*)(srow + (size_t)m0 * Ll + n0)       = lo;
            *(__nv_bfloat162*)(srow + (size_t)(m0 + 8) * Ll + n0) = hi;
        }
    }
}

// ============================================================
// Exact top-k + softmax + V gather, gated by approx scores.
// block = (qtile 128, bh). 128 threads (1 per query).
// Exact scores recomputed with the R8-identical fmaf chain.
// ============================================================
#define KMARGIN 0.0625f

// dynamic smem layout (floats):
#define K2_SQ   0                    // [128][65] fp32
#define K2_SAPP (K2_SQ + 128*65)     // [128][66] bf16 (occupies 128*33 floats)
#define K2_SAV  (K2_SAPP + 128*33)   // [128][33] fp32
#define K2_STV  (K2_SAV + 128*33)
#define K2_STI  (K2_STV + 128*33)
#define K2_FLOATS (K2_STI + 128*33)

__global__ __launch_bounds__(128) void topk_attn_kernel(
    const float* __restrict__ gq, const float* __restrict__ gk,
    const float* __restrict__ gv, const __nv_bfloat16* __restrict__ sapp,
    float* __restrict__ gao)
{
    extern __shared__ float sm[];
    float* sQ  = sm + K2_SQ;
    __nv_bfloat16* sApp = (__nv_bfloat16*)(sm + K2_SAPP);
    float* sAV = sm + K2_SAV;
    float* sTV = sm + K2_STV;
    int*   sTI = (int*)(sm + K2_STI);

    const int tid = threadIdx.x;
    const int bh  = blockIdx.y;
    const int b   = bh >> 4;
    const int h   = bh & 15;
    const int l0  = blockIdx.x * 128;

    // load q rows (fp32) for exact rescoring
    for (int idx = tid; idx < 128 * 64; idx += 128) {
        int q = idx >> 6;
        int d = idx & 63;
        sQ[q * 65 + d] = gq[((size_t)(b * Ll + l0 + q)) * Ee + h * 64 + d];
    }
    #pragma unroll
    for (int j = 0; j < TOPKk; j++) {
        sAV[tid * 33 + j] = -INFINITY;
        sTV[tid * 33 + j] = -INFINITY;
        sTI[tid * 33 + j] = 0;
    }
    __syncthreads();

    const __nv_bfloat16* srow = sapp + ((size_t)bh * Ll + l0) * Ll;

    // ---- pass 1: approx top-32 (values only) ----
    float aMin = -INFINITY;
    int   aPos = 0;
    for (int kt = 0; kt < 16; kt++) {
        for (int it = 0; it < 32; it++) {
            int idx = tid + it * 128;         // 0..4095
            int q = idx >> 5;
            int seg = idx & 31;
            *(__nv_bfloat162*)(sApp + q * 66 + seg * 2) =
                *(const __nv_bfloat162*)(srow + (size_t)q * Ll + kt * 64 + seg * 2);
        }
        __syncthreads();
        #pragma unroll 1
        for (int kk = 0; kk < 64; kk++) {
            float a = __bfloat162float(sApp[tid * 66 + kk]);
            if (a > aMin) {
                sAV[tid * 33 + aPos] = a;
                float mn = sAV[tid * 33];
                int   mp = 0;
                #pragma unroll
                for (int j = 1; j < TOPKk; j++) {
                    float v = sAV[tid * 33 + j];
                    if (v < mn) { mn = v; mp = j; }
                }
                aMin = mn; aPos = mp;
            }
        }
        __syncthreads();
    }
    const float tau = aMin - KMARGIN;

    // ---- pass 2: exact rescore of gated candidates, exact top-32 ----
    float eMin = -INFINITY;
    int   ePos = 0;
    for (int kt = 0; kt < 16; kt++) {
        for (int it = 0; it < 32; it++) {
            int idx = tid + it * 128;
            int q = idx >> 5;
            int seg = idx & 31;
            *(__nv_bfloat162*)(sApp + q * 66 + seg * 2) =
                *(const __nv_bfloat162*)(srow + (size_t)q * Ll + kt * 64 + seg * 2);
        }
        __syncthreads();
        #pragma unroll 1
        for (int kk = 0; kk < 64; kk++) {
            float a = __bfloat162float(sApp[tid * 66 + kk]);
            if (a >= tau) {
                const int key = kt * 64 + kk;
                const float4* kr = (const float4*)(gk + ((size_t)(b * Ll + key)) * Ee + h * 64);
                float acc = 0.0f;
                #pragma unroll
                for (int d4 = 0; d4 < 16; d4++) {
                    float4 kv = kr[d4];
                    acc = fmaf(sQ[tid * 65 + d4 * 4 + 0], kv.x, acc);
                    acc = fmaf(sQ[tid * 65 + d4 * 4 + 1], kv.y, acc);
                    acc = fmaf(sQ[tid * 65 + d4 * 4 + 2], kv.z, acc);
                    acc = fmaf(sQ[tid * 65 + d4 * 4 + 3], kv.w, acc);
                }
                float s = acc * 0.125f;
                if (s > eMin) {
                    sTV[tid * 33 + ePos] = s;
                    sTI[tid * 33 + ePos] = key;
                    float mn = sTV[tid * 33];
                    int   mp = 0;
                    #pragma unroll
                    for (int j = 1; j < TOPKk; j++) {
                        float v = sTV[tid * 33 + j];
                        if (v < mn) { mn = v; mp = j; }
                    }
                    eMin = mn; ePos = mp;
                }
            }
        }
        __syncthreads();
    }

    // ---- epilogue: warp per query softmax + V gather ----
    const int warp = tid >> 5;
    const int lane = tid & 31;
    for (int qi = warp; qi < 128; qi += 4) {
        float v  = sTV[qi * 33 + lane];
        int   ki = sTI[qi * 33 + lane];

        float mx = v;
        #pragma unroll
        for (int o = 16; o; o >>= 1) mx = fmaxf(mx, __shfl_xor_sync(0xffffffffu, mx, o));
        float e = expf(v - mx);
        float se = e;
        #pragma unroll
        for (int o = 16; o; o >>= 1) se += __shfl_xor_sync(0xffffffffu, se, o);
        float w = e / se;

        float a0 = 0.f, a1 = 0.f;
        #pragma unroll
        for (int j = 0; j < TOPKk; j++) {
            float wj = __shfl_sync(0xffffffffu, w, j);
            int   kj = __shfl_sync(0xffffffffu, ki, j);
            const float* vr = gv + ((size_t)(b * Ll + kj)) * Ee + h * 64;
            a0 = fmaf(wj, vr[lane],      a0);
            a1 = fmaf(wj, vr[lane + 32], a1);
        }
        float* op = gao + ((size_t)(b * Ll + l0 + qi)) * Ee + h * 64;
        op[lane]      = a0;
        op[lane + 32] = a1;
    }
}

// ============================================================
extern "C" void kernel_launch(void* const* d_in, const int* in_sizes, int n_in,
                              void* d_out, int out_size)
{
    const float* Q  = (const float*)d_in[0];
    const float* K_ = (const float*)d_in[1];
    const float* V  = (const float*)d_in[2];
    const float* Wq = (const float*)d_in[3];
    const float* bq = (const float*)d_in[4];
    const float* Wk = (const float*)d_in[5];
    const float* bk = (const float*)d_in[6];
    const float* Wv = (const float*)d_in[7];
    const float* bv = (const float*)d_in[8];
    const float* Wo = (const float*)d_in[9];
    const float* bo = (const float*)d_in[10];
    float* out = (float*)d_out;

    float *gq, *gk, *gv, *gao;
    cudaGetSymbolAddress((void**)&gq,  g_q);
    cudaGetSymbolAddress((void**)&gk,  g_k);
    cudaGetSymbolAddress((void**)&gv,  g_v);
    cudaGetSymbolAddress((void**)&gao, g_ao);
    __nv_bfloat16 *vs1, *vs2, *wv1, *wv2, *wo1, *wo2, *qb, *kb, *sapp;
    cudaGetSymbolAddress((void**)&vs1, g_vs1);
    cudaGetSymbolAddress((void**)&vs2, g_vs2);
    cudaGetSymbolAddress((void**)&wv1, g_wv1);
    cudaGetSymbolAddress((void**)&wv2, g_wv2);
    cudaGetSymbolAddress((void**)&wo1, g_wo1);
    cudaGetSymbolAddress((void**)&wo2, g_wo2);
    cudaGetSymbolAddress((void**)&qb,  g_qb);
    cudaGetSymbolAddress((void**)&kb,  g_kb);
    cudaGetSymbolAddress((void**)&sapp, g_sapp);

    static cudaStream_t sV = nullptr;
    static cudaEvent_t eFork = nullptr, eV = nullptr;
    if (sV == nullptr) {
        cudaStreamCreateWithFlags(&sV, cudaStreamNonBlocking);
        cudaEventCreateWithFlags(&eFork, cudaEventDisableTiming);
        cudaEventCreateWithFlags(&eV, cudaEventDisableTiming);
    }

    const int M = Bb * Ll;   // 4096
    const int N = Ee;        // 1024
    const int K = Ee;        // 1024

    dim3 gblock(256);
    dim3 ggrid(N / GBN, M / GBM);
    dim3 tgrid(N / 128, M / 128);

    cudaFuncSetAttribute(gemm_bf16x2_mma,
                         cudaFuncAttributeMaxDynamicSharedMemorySize, TG_SMEM);
    const int k2Smem = K2_FLOATS * sizeof(float);   // ~101 KB
    cudaFuncSetAttribute(topk_attn_kernel,
                         cudaFuncAttributeMaxDynamicSharedMemorySize, k2Smem);

    // ---- fork: v-path on side stream ----
    cudaEventRecord(eFork, 0);
    cudaStreamWaitEvent(sV, eFork, 0);

    split2_kernel<<<(M*K + 255)/256, 256, 0, sV>>>(V,  vs1, vs2, M*K);
    split2_kernel<<<(N*K + 255)/256, 256, 0, sV>>>(Wv, wv1, wv2, N*K);
    gemm_bf16x2_mma<<<tgrid, 256, TG_SMEM, sV>>>(vs1, vs2, wv1, wv2, bv, gv);
    split2_kernel<<<(N*K + 255)/256, 256, 0, sV>>>(Wo, wo1, wo2, N*K);
    cudaEventRecord(eV, sV);

    // ---- main: q, k projections (scalar fp32, bit-identical) ----
    gemm_nt_bias<<<ggrid, gblock>>>(Q,  Wq, bq, gq, M, N, K);
    gemm_nt_bias<<<ggrid, gblock>>>(K_, Wk, bk, gk, M, N, K);

    // bf16 casts for the approx filter
    cast_bf16_kernel<<<(M*K + 255)/256, 256>>>(gq, qb, M*K);
    cast_bf16_kernel<<<(M*K + 255)/256, 256>>>(gk, kb, M*K);

    // approx logits via tensor cores
    dim3 fgrid(Ll / 128, Ll / 128, Bb * Hh);   // (8, 8, 64)
    filter_scores_kernel<<<fgrid, 256>>>(qb, kb, sapp);

    // join: epilogue gathers V from side stream
    cudaStreamWaitEvent(0, eV, 0);

    // exact top-k + softmax + V (selection identical to full scan)
    dim3 agrid(Ll / 128, Bb * Hh);   // (8, 64)
    topk_attn_kernel<<<agrid, 128, k2Smem>>>(gq, gk, gv, sapp, gao);

    // ---- output projection (3-term bf16x2) ----
    split2_kernel<<<(M*K + 255)/256, 256>>>(gao, vs1, vs2, M*K);
    gemm_bf16x2_mma<<<tgrid, 256, TG_SMEM>>>(vs1, vs2, wo1, wo2, bo, out);
}